// round 5
// baseline (speedup 1.0000x reference)
#include <cuda_runtime.h>
#include <cuda_bf16.h>

// InterLayerTrajectoryFlow: fused diff -> normalize -> causal 6-tap weighted sum.
// emb: [B, S, D] fp32, S=8192, D=512.
//
// Smem-tile design at full occupancy: block = (batch, 16-position chunk),
// 512 threads (one feature column each). Diffs live in a 42KB smem tile;
// the squared-norm reduction is fused into the load loop (2-stage shuffle
// -> 128 partials/row), so the tile is written once and read once.
// 54.5KB smem + <=32 regs -> 4 blocks/SM (2048 threads, 100% occupancy).

#define S_LEN 8192
#define D_DIM 512
#define PC 16                 // positions per block
#define ER (PC + 6)           // 22 embedding rows (chunk + halo)
#define DR (PC + 5)           // 21 diff rows
#define WIN 6
#define PSTR 132              // 128 partials per row, padded stride

#define SMEM_FLOATS (DR * D_DIM + DR * PSTR + 24 + PC * WIN)
#define SMEM_BYTES (SMEM_FLOATS * 4)

__global__ __launch_bounds__(512, 4)
void traj_flow_kernel(const float* __restrict__ emb,
                      const int* __restrict__ layer_idx,
                      float* __restrict__ out) {
    extern __shared__ float sm[];
    float* sdiff = sm;                          // [DR][D_DIM]  42 KB
    float* spart = sm + DR * D_DIM;             // [DR][PSTR]   ~11 KB
    float* srinv = spart + DR * PSTR;           // [DR] (pad 24)
    float* scw   = srinv + 24;                  // [PC][WIN]

    const int col  = threadIdx.x;               // 0..511 = feature column
    const int lane = col & 31;
    const int wid  = col >> 5;
    const int b    = blockIdx.y;
    const int pos0 = blockIdx.x * PC;

    // ---- Phase 1: load rows, write diffs to smem, fused 2-stage norm partials ----
    {
        const int gr0 = pos0 - WIN;
        const float* ep = emb + ((long long)(b * S_LEN + gr0)) * D_DIM + col;
        float prev = 0.0f;
        #pragma unroll
        for (int r = 0; r < ER; ++r) {
            float cur = (gr0 + r >= 0) ? ep[r * D_DIM] : 0.0f;
            if (r > 0) {
                const float d = cur - prev;
                sdiff[(r - 1) * D_DIM + col] = d;
                float s = d * d;
                s += __shfl_xor_sync(0xffffffffu, s, 16);
                s += __shfl_xor_sync(0xffffffffu, s, 8);
                if (lane < 8)
                    spart[(r - 1) * PSTR + wid * 8 + lane] = s;  // {l,l^8,l^16,l^24}
            }
            prev = cur;
        }
    }
    __syncthreads();

    // ---- Phase 2: combine 128 partials per row (16 warps cover 21 rows) ----
    for (int r = wid; r < DR; r += 16) {
        const float* pp = spart + r * PSTR;
        float s = pp[lane] + pp[lane + 32] + pp[lane + 64] + pp[lane + 96];
        #pragma unroll
        for (int o = 16; o > 0; o >>= 1)
            s += __shfl_xor_sync(0xffffffffu, s, o);
        if (lane == 0) {
            const float mag = sqrtf(s);
            srinv[r] = (mag > 1e-6f) ? (1.0f / (mag + 1e-8f)) : 0.0f;
        }
    }
    __syncthreads();

    // ---- Phase 3: fused coefficients cw[lp][k] ----
    if (col < PC * WIN) {
        const int lp  = col / WIN;
        const int k   = col % WIN;
        const int pos = pos0 + lp;
        float c = 0.0f;
        const int w = (pos < WIN) ? pos : WIN;
        if (pos >= 1 && k < w) {
            const float ds = 0.1f * (1.0f + (float)(*layer_idx) * 0.8f);
            float Wk, wsum;
            if (w == 1) {
                Wk = expf(-1.0f);
                wsum = Wk;
            } else {
                const float dn = (float)(w - 1);
                wsum = 0.0f;
                for (int j = 0; j < w; ++j) wsum += expf(-(float)j / dn);
                Wk = expf(-(float)k / dn);
            }
            // diff used: global index pos-1-k -> tile row lp + 5 - k
            c = Wk / (wsum + 1e-8f) * ds * srinv[lp + 5 - k];
        }
        scw[col] = c;
    }
    __syncthreads();

    // ---- Phase 4: sliding 6-register window over smem tile, coalesced stores ----
    {
        float win[WIN];
        #pragma unroll
        for (int i = 0; i < WIN; ++i) win[i] = sdiff[i * D_DIM + col];

        float* op = out + ((long long)(b * S_LEN + pos0)) * D_DIM + col;
        #pragma unroll
        for (int lp = 0; lp < PC; ++lp) {
            float acc = 0.0f;
            #pragma unroll
            for (int k = 0; k < WIN; ++k)
                acc = fmaf(scw[lp * WIN + k], win[5 - k], acc);
            op[lp * D_DIM] = acc;
            #pragma unroll
            for (int i = 0; i < WIN - 1; ++i) win[i] = win[i + 1];
            if (lp < PC - 1)
                win[WIN - 1] = sdiff[(lp + WIN) * D_DIM + col];
        }
    }
}

extern "C" void kernel_launch(void* const* d_in, const int* in_sizes, int n_in,
                              void* d_out, int out_size) {
    const float* emb = (const float*)d_in[0];
    const int* layer_idx = (const int*)d_in[1];
    float* out = (float*)d_out;

    const int B = in_sizes[0] / (S_LEN * D_DIM);

    cudaFuncSetAttribute(traj_flow_kernel,
                         cudaFuncAttributeMaxDynamicSharedMemorySize, SMEM_BYTES);

    dim3 grid(S_LEN / PC, B);
    traj_flow_kernel<<<grid, D_DIM, SMEM_BYTES>>>(emb, layer_idx, out);
}

// round 6
// speedup vs baseline: 1.2308x; 1.2308x over previous
#include <cuda_runtime.h>
#include <cuda_bf16.h>

// InterLayerTrajectoryFlow: fused diff -> normalize -> causal 6-tap weighted sum.
// emb: [B, S, D] fp32, S=8192, D=512.
//
// Vectorized (float4) smem-tile design: block = (batch, 32-position chunk),
// 512 threads = 4 row-phases x 128 column-groups (16B each). The 38-row load
// is split across phases; diffs go to a 76KB smem tile as float4 with the
// squared-norm reduction fused into the load (3-stage shuffle -> 16
// partials/row). Output: each phase handles 8 positions with a sliding
// float4 window -> ~45 LSU ops/thread (vs ~170 scalar).

#define S_LEN 8192
#define D_DIM 512
#define C4 128                // float4 column groups per row
#define PC 32                 // positions per block
#define ER (PC + 6)           // 38 embedding rows
#define DR (PC + 5)           // 37 diff rows
#define WIN 6

#define SMEM_FLOATS (DR * D_DIM + DR * 16 + 40 + PC * WIN)
#define SMEM_BYTES (SMEM_FLOATS * 4)

__global__ __launch_bounds__(512, 2)
void traj_flow_kernel(const float* __restrict__ emb,
                      const int* __restrict__ layer_idx,
                      float* __restrict__ out) {
    extern __shared__ float sm[];
    float4* sdiff4 = (float4*)sm;              // [DR][C4] float4 tile
    float*  spart  = sm + DR * D_DIM;          // [DR][16] partial sums
    float*  srinv  = spart + DR * 16;          // [DR] (pad 40)
    float*  scw    = srinv + 40;               // [PC][WIN]

    const int tid   = threadIdx.x;
    const int c4    = tid & (C4 - 1);          // column group 0..127
    const int phase = tid >> 7;                // row phase 0..3
    const int lane  = tid & 31;
    const int wip   = (tid >> 5) & 3;          // warp within phase
    const int wid   = tid >> 5;
    const int b     = blockIdx.y;
    const int pos0  = blockIdx.x * PC;

    // ---- Phase 1: vectorized load (4 row-phases), diffs -> smem, fused partials ----
    {
        const int ps = phase ? (1 + phase * 9) : 0;     // first row this phase loads
        const int pn = phase ? 10 : 11;                 // rows this phase loads
        const int gr0 = pos0 - WIN + ps;                // global row of first load
        const float4* ep = (const float4*)emb
                         + ((long long)(b * S_LEN + gr0)) * C4 + c4;
        float4 prev = make_float4(0.f, 0.f, 0.f, 0.f);
        #pragma unroll
        for (int i = 0; i < 11; ++i) {
            if (i < pn) {
                float4 cur = (gr0 + i >= 0) ? ep[i * C4]
                                            : make_float4(0.f, 0.f, 0.f, 0.f);
                if (i > 0) {
                    float4 d = make_float4(cur.x - prev.x, cur.y - prev.y,
                                           cur.z - prev.z, cur.w - prev.w);
                    const int dr = ps + i - 1;          // diff row 0..36
                    sdiff4[dr * C4 + c4] = d;
                    float s = d.x * d.x + d.y * d.y + d.z * d.z + d.w * d.w;
                    s += __shfl_xor_sync(0xffffffffu, s, 16);
                    s += __shfl_xor_sync(0xffffffffu, s, 8);
                    s += __shfl_xor_sync(0xffffffffu, s, 4);
                    if (lane < 4)
                        spart[dr * 16 + wip * 4 + lane] = s;
                }
                prev = cur;
            }
        }
    }
    __syncthreads();

    // ---- Phase 2: combine 16 partials per diff row -> inverse norm ----
    for (int r = wid; r < DR; r += 16) {
        float s = (lane < 16) ? spart[r * 16 + lane] : 0.0f;
        s += __shfl_xor_sync(0xffffffffu, s, 8);
        s += __shfl_xor_sync(0xffffffffu, s, 4);
        s += __shfl_xor_sync(0xffffffffu, s, 2);
        s += __shfl_xor_sync(0xffffffffu, s, 1);
        if (lane == 0) {
            const float mag = sqrtf(s);
            srinv[r] = (mag > 1e-6f) ? (1.0f / (mag + 1e-8f)) : 0.0f;
        }
    }
    __syncthreads();

    // ---- Phase 3: fused coefficients cw[lp][k] ----
    if (tid < PC * WIN) {
        const int lp  = tid / WIN;
        const int k   = tid % WIN;
        const int pos = pos0 + lp;
        float c = 0.0f;
        const int w = (pos < WIN) ? pos : WIN;
        if (pos >= 1 && k < w) {
            const float ds = 0.1f * (1.0f + (float)(*layer_idx) * 0.8f);
            float Wk, wsum;
            if (w == 1) {
                Wk = expf(-1.0f);
                wsum = Wk;
            } else {
                const float dn = (float)(w - 1);
                wsum = 0.0f;
                for (int j = 0; j < w; ++j) wsum += expf(-(float)j / dn);
                Wk = expf(-(float)k / dn);
            }
            // diff used: global index pos-1-k -> tile row lp + 5 - k
            c = Wk / (wsum + 1e-8f) * ds * srinv[lp + 5 - k];
        }
        scw[tid] = c;
    }
    __syncthreads();

    // ---- Phase 4: each phase emits 8 positions, sliding float4 window ----
    {
        const int lp0 = phase * 8;
        float4 win[WIN];
        #pragma unroll
        for (int i = 0; i < WIN; ++i)
            win[i] = sdiff4[(lp0 + i) * C4 + c4];

        float4* op = (float4*)out
                   + ((long long)(b * S_LEN + pos0 + lp0)) * C4 + c4;
        #pragma unroll
        for (int j = 0; j < 8; ++j) {
            const int lp = lp0 + j;
            float4 acc = make_float4(0.f, 0.f, 0.f, 0.f);
            #pragma unroll
            for (int k = 0; k < WIN; ++k) {
                const float c = scw[lp * WIN + k];
                const float4 w = win[5 - k];
                acc.x = fmaf(c, w.x, acc.x);
                acc.y = fmaf(c, w.y, acc.y);
                acc.z = fmaf(c, w.z, acc.z);
                acc.w = fmaf(c, w.w, acc.w);
            }
            op[j * C4] = acc;
            #pragma unroll
            for (int i = 0; i < WIN - 1; ++i) win[i] = win[i + 1];
            if (j < 7)
                win[WIN - 1] = sdiff4[(lp + WIN) * C4 + c4];
        }
    }
}

extern "C" void kernel_launch(void* const* d_in, const int* in_sizes, int n_in,
                              void* d_out, int out_size) {
    const float* emb = (const float*)d_in[0];
    const int* layer_idx = (const int*)d_in[1];
    float* out = (float*)d_out;

    const int B = in_sizes[0] / (S_LEN * D_DIM);

    cudaFuncSetAttribute(traj_flow_kernel,
                         cudaFuncAttributeMaxDynamicSharedMemorySize, SMEM_BYTES);

    dim3 grid(S_LEN / PC, B);
    traj_flow_kernel<<<grid, D_DIM, SMEM_BYTES>>>(emb, layer_idx, out);
}

// round 7
// speedup vs baseline: 1.2813x; 1.0411x over previous
#include <cuda_runtime.h>
#include <cuda_bf16.h>

// InterLayerTrajectoryFlow: fused diff -> normalize -> causal 6-tap weighted sum.
// emb: [B, S, D] fp32, S=8192, D=512.
//
// Vectorized (float4) smem-tile design with 4 barrier domains per SM:
// block = (batch, 16-position chunk), 256 threads = 2 row-phases x 128
// float4 column groups. Diffs -> 42KB smem tile with the squared-norm
// reduction fused into the load (3-stage shuffle -> 16 partials/row).
// 4 blocks/SM desynchronize the barrier/compute phases so DRAM stays busy.

#define S_LEN 8192
#define D_DIM 512
#define C4 128                // float4 column groups per row
#define PC 16                 // positions per block
#define ER (PC + 6)           // 22 embedding rows
#define DR (PC + 5)           // 21 diff rows
#define WIN 6

#define SMEM_FLOATS (DR * D_DIM + DR * 16 + 24 + PC * WIN)
#define SMEM_BYTES (SMEM_FLOATS * 4)

__global__ __launch_bounds__(256, 4)
void traj_flow_kernel(const float* __restrict__ emb,
                      const int* __restrict__ layer_idx,
                      float* __restrict__ out) {
    extern __shared__ float sm[];
    float4* sdiff4 = (float4*)sm;              // [DR][C4] float4 tile (42KB)
    float*  spart  = sm + DR * D_DIM;          // [DR][16] partial sums
    float*  srinv  = spart + DR * 16;          // [DR] (pad 24)
    float*  scw    = srinv + 24;               // [PC][WIN]

    const int tid   = threadIdx.x;
    const int c4    = tid & (C4 - 1);          // column group 0..127
    const int phase = tid >> 7;                // row phase 0..1
    const int lane  = tid & 31;
    const int wip   = (tid >> 5) & 3;          // warp within phase (0..3)
    const int wid   = tid >> 5;                // warp id 0..7
    const int b     = blockIdx.y;
    const int pos0  = blockIdx.x * PC;

    // ---- Phase 1: vectorized load (2 row-phases), diffs -> smem, fused partials ----
    {
        const int ps  = phase ? 11 : 0;        // first row this phase loads
        const int pn  = phase ? 11 : 12;       // rows this phase loads
        const int gr0 = pos0 - WIN + ps;       // global row of first load
        const float4* ep = (const float4*)emb
                         + ((long long)(b * S_LEN + gr0)) * C4 + c4;
        float4 prev = make_float4(0.f, 0.f, 0.f, 0.f);
        #pragma unroll
        for (int i = 0; i < 12; ++i) {
            if (i < pn) {
                float4 cur = (gr0 + i >= 0) ? ep[i * C4]
                                            : make_float4(0.f, 0.f, 0.f, 0.f);
                if (i > 0) {
                    float4 d = make_float4(cur.x - prev.x, cur.y - prev.y,
                                           cur.z - prev.z, cur.w - prev.w);
                    const int dr = ps + i - 1;          // diff row 0..20
                    sdiff4[dr * C4 + c4] = d;
                    float s = d.x * d.x + d.y * d.y + d.z * d.z + d.w * d.w;
                    s += __shfl_xor_sync(0xffffffffu, s, 16);
                    s += __shfl_xor_sync(0xffffffffu, s, 8);
                    s += __shfl_xor_sync(0xffffffffu, s, 4);
                    if (lane < 4)
                        spart[dr * 16 + wip * 4 + lane] = s;
                }
                prev = cur;
            }
        }
    }
    __syncthreads();

    // ---- Phase 2: combine 16 partials per diff row -> inverse norm ----
    for (int r = wid; r < DR; r += 8) {
        float s = (lane < 16) ? spart[r * 16 + lane] : 0.0f;
        s += __shfl_xor_sync(0xffffffffu, s, 8);
        s += __shfl_xor_sync(0xffffffffu, s, 4);
        s += __shfl_xor_sync(0xffffffffu, s, 2);
        s += __shfl_xor_sync(0xffffffffu, s, 1);
        if (lane == 0) {
            const float mag = sqrtf(s);
            srinv[r] = (mag > 1e-6f) ? (1.0f / (mag + 1e-8f)) : 0.0f;
        }
    }
    __syncthreads();

    // ---- Phase 3: fused coefficients cw[lp][k] ----
    if (tid < PC * WIN) {
        const int lp  = tid / WIN;
        const int k   = tid % WIN;
        const int pos = pos0 + lp;
        float c = 0.0f;
        const int w = (pos < WIN) ? pos : WIN;
        if (pos >= 1 && k < w) {
            const float ds = 0.1f * (1.0f + (float)(*layer_idx) * 0.8f);
            float Wk, wsum;
            if (w == 1) {
                Wk = expf(-1.0f);
                wsum = Wk;
            } else {
                const float dn = (float)(w - 1);
                wsum = 0.0f;
                for (int j = 0; j < w; ++j) wsum += expf(-(float)j / dn);
                Wk = expf(-(float)k / dn);
            }
            // diff used: global index pos-1-k -> tile row lp + 5 - k
            c = Wk / (wsum + 1e-8f) * ds * srinv[lp + 5 - k];
        }
        scw[tid] = c;
    }
    __syncthreads();

    // ---- Phase 4: each phase emits 8 positions, sliding float4 window ----
    {
        const int lp0 = phase * 8;
        float4 win[WIN];
        #pragma unroll
        for (int i = 0; i < WIN; ++i)
            win[i] = sdiff4[(lp0 + i) * C4 + c4];

        float4* op = (float4*)out
                   + ((long long)(b * S_LEN + pos0 + lp0)) * C4 + c4;
        #pragma unroll
        for (int j = 0; j < 8; ++j) {
            const int lp = lp0 + j;
            float4 acc = make_float4(0.f, 0.f, 0.f, 0.f);
            #pragma unroll
            for (int k = 0; k < WIN; ++k) {
                const float c = scw[lp * WIN + k];
                const float4 w = win[5 - k];
                acc.x = fmaf(c, w.x, acc.x);
                acc.y = fmaf(c, w.y, acc.y);
                acc.z = fmaf(c, w.z, acc.z);
                acc.w = fmaf(c, w.w, acc.w);
            }
            op[j * C4] = acc;
            #pragma unroll
            for (int i = 0; i < WIN - 1; ++i) win[i] = win[i + 1];
            if (j < 7)
                win[WIN - 1] = sdiff4[(lp + WIN) * C4 + c4];
        }
    }
}

extern "C" void kernel_launch(void* const* d_in, const int* in_sizes, int n_in,
                              void* d_out, int out_size) {
    const float* emb = (const float*)d_in[0];
    const int* layer_idx = (const int*)d_in[1];
    float* out = (float*)d_out;

    const int B = in_sizes[0] / (S_LEN * D_DIM);

    cudaFuncSetAttribute(traj_flow_kernel,
                         cudaFuncAttributeMaxDynamicSharedMemorySize, SMEM_BYTES);

    dim3 grid(S_LEN / PC, B);
    traj_flow_kernel<<<grid, 256, SMEM_BYTES>>>(emb, layer_idx, out);
}